// round 2
// baseline (speedup 1.0000x reference)
#include <cuda_runtime.h>
#include <math.h>

#define N_NODES 100000
#define SEQ 16

// Scratch activations (device globals: no allocation allowed).
__device__ float g_h0[N_NODES * 16];
__device__ float g_h1[N_NODES * 32];
__device__ float g_h2[N_NODES * 64];
__device__ float g_h3[N_NODES * 128];
__device__ float g_h4[N_NODES * 256];
__device__ int   g_idx[N_NODES * SEQ];
__device__ int   g_is64;

__device__ __forceinline__ float elu(float v) {
    return v > 0.f ? v : expm1f(v);
}

// ---------------------------------------------------------------------------
// Index dtype detection + conversion.
// The reference declares int64 but JAX default (x64 off) yields int32.
// If int64 (little-endian, values < 2^31), every odd 32-bit word is 0.
// Sample 64 odd words within the first 1.6M words (valid either way).
// ---------------------------------------------------------------------------
__global__ void detect_idx_kernel(const int* __restrict__ w32) {
    if (threadIdx.x == 0) {
        int all_zero = 1;
        for (int k = 0; k < 64; k++) {
            if (w32[2 * k * 1024 + 1] != 0) { all_zero = 0; break; }
        }
        g_is64 = all_zero;
    }
}

__global__ void conv_idx_kernel(const int* __restrict__ w32) {
    int i = blockIdx.x * blockDim.x + threadIdx.x;
    if (i >= N_NODES * SEQ) return;
    int v = g_is64 ? w32[2 * i] : w32[i];
    if (v < 0) v = 0;
    if (v >= N_NODES) v = N_NODES - 1;
    g_idx[i] = v;
}

// ---------------------------------------------------------------------------
// fc0: [N,3] @ [3,16]^T + b, ELU. One thread per node.
// ---------------------------------------------------------------------------
__global__ __launch_bounds__(256) void fc0_kernel(
    const float* __restrict__ x,
    const float* __restrict__ w,
    const float* __restrict__ bias)
{
    __shared__ float sw[48];
    __shared__ float sb[16];
    if (threadIdx.x < 48) sw[threadIdx.x] = w[threadIdx.x];
    if (threadIdx.x < 16) sb[threadIdx.x] = bias[threadIdx.x];
    __syncthreads();

    int n = blockIdx.x * blockDim.x + threadIdx.x;
    if (n >= N_NODES) return;

    float x0 = x[n * 3 + 0], x1 = x[n * 3 + 1], x2 = x[n * 3 + 2];
    float o[16];
#pragma unroll
    for (int j = 0; j < 16; j++) {
        float v = sb[j] + sw[j * 3 + 0] * x0 + sw[j * 3 + 1] * x1 + sw[j * 3 + 2] * x2;
        o[j] = elu(v);
    }
    float4* dst = reinterpret_cast<float4*>(g_h0 + (size_t)n * 16);
#pragma unroll
    for (int q = 0; q < 4; q++)
        dst[q] = make_float4(o[4 * q], o[4 * q + 1], o[4 * q + 2], o[4 * q + 3]);
}

// ---------------------------------------------------------------------------
// Gathered GEMM + bias + ELU.
//   out[n, o] = elu( sum_k A[n,k] * w[o,k] + b[o] )
//   A[n,k] = GATHER ? prev[idx[n, k/C] * C + k%C] : prev[n*K + k]
//
// BN=64 nodes/block, OT outputs/block (blockIdx.y tiles O), BK=32,
// 256 threads. tx=t&15, ty=t>>4; microtile TM=4 nodes x TO=OT/16 outputs,
// strided-by-16 => conflict-free smem reads, contiguous smem stores.
// ---------------------------------------------------------------------------
template <int C, int K, int O_TOTAL, int OT, bool GATHER>
__global__ __launch_bounds__(256) void gemm_elu_kernel(
    const float* __restrict__ prev,
    float* __restrict__ next,
    const float* __restrict__ w,
    const float* __restrict__ bias)
{
    constexpr int BN = 64, BK = 32, TM = 4;
    constexpr int TO = OT / 16;

    __shared__ float sA[BN][BK + 1];
    __shared__ float sB[OT][BK + 1];
    __shared__ int   sIdx[GATHER ? BN * SEQ : 1];

    const int n0    = blockIdx.x * BN;
    const int o_off = blockIdx.y * OT;
    const int t  = threadIdx.x;
    const int tx = t & 15;
    const int ty = t >> 4;

    if constexpr (GATHER) {
#pragma unroll
        for (int i = t; i < BN * SEQ; i += 256) {
            int node = n0 + (i >> 4);            // SEQ == 16
            if (node > N_NODES - 1) node = N_NODES - 1;
            sIdx[i] = g_idx[node * SEQ + (i & 15)];
        }
        __syncthreads();
    }

    float acc[TM][TO];
#pragma unroll
    for (int i = 0; i < TM; i++)
#pragma unroll
        for (int j = 0; j < TO; j++) acc[i][j] = 0.f;

    for (int k0 = 0; k0 < K; k0 += BK) {
        // A tile (gathered): 32 consecutive threads cover one node's 32
        // contiguous k => coalesced 128B reads from the gathered row.
#pragma unroll
        for (int r = 0; r < (BN * BK) / 256; r++) {
            int linear = r * 256 + t;
            int nrow = linear >> 5;
            int kk   = linear & 31;
            int k    = k0 + kk;
            float v;
            if constexpr (GATHER) {
                int src = sIdx[nrow * SEQ + (k / C)];
                v = prev[(size_t)src * C + (k % C)];
            } else {
                int node = n0 + nrow;
                if (node > N_NODES - 1) node = N_NODES - 1;
                v = prev[(size_t)node * K + k];
            }
            sA[nrow][kk] = v;
        }
        // B tile: w is [O_TOTAL, K] row-major, contiguous along k.
#pragma unroll
        for (int r = 0; r < (OT * BK) / 256; r++) {
            int linear = r * 256 + t;
            int o  = linear >> 5;
            int kk = linear & 31;
            sB[o][kk] = w[(size_t)(o_off + o) * K + k0 + kk];
        }
        __syncthreads();

#pragma unroll
        for (int kk = 0; kk < BK; kk++) {
            float a[TM], bb[TO];
#pragma unroll
            for (int i = 0; i < TM; i++) a[i] = sA[ty + 16 * i][kk];
#pragma unroll
            for (int j = 0; j < TO; j++) bb[j] = sB[tx + 16 * j][kk];
#pragma unroll
            for (int i = 0; i < TM; i++)
#pragma unroll
                for (int j = 0; j < TO; j++)
                    acc[i][j] = fmaf(a[i], bb[j], acc[i][j]);
        }
        __syncthreads();
    }

    // Epilogue: bias + ELU, coalesced within 16-thread groups.
#pragma unroll
    for (int j = 0; j < TO; j++) {
        float bv = bias[o_off + tx + 16 * j];
#pragma unroll
        for (int i = 0; i < TM; i++) {
            int node = n0 + ty + 16 * i;
            if (node < N_NODES)
                next[(size_t)node * O_TOTAL + o_off + tx + 16 * j] =
                    elu(acc[i][j] + bv);
        }
    }
}

// ---------------------------------------------------------------------------
// fc2 + log_softmax: one warp per node. 12 outputs from 256 inputs.
// ---------------------------------------------------------------------------
__global__ __launch_bounds__(256) void fc2_lsm_kernel(
    const float* __restrict__ w,
    const float* __restrict__ bias,
    float* __restrict__ out)
{
    __shared__ float sw[12][256];
    __shared__ float sb[12];
    int t = threadIdx.x;
    for (int i = t; i < 12 * 256; i += 256) sw[i >> 8][i & 255] = w[i];
    if (t < 12) sb[t] = bias[t];
    __syncthreads();

    int node = blockIdx.x * 8 + (t >> 5);
    int lane = t & 31;
    if (node >= N_NODES) return;

    const float* row = g_h4 + (size_t)node * 256;
    float acc[12];
#pragma unroll
    for (int o = 0; o < 12; o++) acc[o] = 0.f;

#pragma unroll
    for (int r = 0; r < 8; r++) {
        float hv = row[lane + 32 * r];
#pragma unroll
        for (int o = 0; o < 12; o++) acc[o] += hv * sw[o][lane + 32 * r];
    }

#pragma unroll
    for (int o = 0; o < 12; o++) {
#pragma unroll
        for (int d = 16; d > 0; d >>= 1)
            acc[o] += __shfl_xor_sync(0xffffffffu, acc[o], d);
        acc[o] += sb[o];
    }

    float m = acc[0];
#pragma unroll
    for (int o = 1; o < 12; o++) m = fmaxf(m, acc[o]);
    float s = 0.f;
#pragma unroll
    for (int o = 0; o < 12; o++) s += expf(acc[o] - m);
    float lse = m + logf(s);

    if (lane < 12) out[(size_t)node * 12 + lane] = acc[lane] - lse;
}

// ---------------------------------------------------------------------------
// Launch
// ---------------------------------------------------------------------------
extern "C" void kernel_launch(void* const* d_in, const int* in_sizes, int n_in,
                              void* d_out, int out_size)
{
    const float* x      = (const float*)d_in[0];
    const int*   idxw   = (const int*)d_in[1];     // int32 words (dtype detected on device)
    const float* fc0_w  = (const float*)d_in[2];
    const float* fc0_b  = (const float*)d_in[3];
    const float* w1     = (const float*)d_in[4];
    const float* b1     = (const float*)d_in[5];
    const float* w2     = (const float*)d_in[6];
    const float* b2     = (const float*)d_in[7];
    const float* w3     = (const float*)d_in[8];
    const float* b3     = (const float*)d_in[9];
    const float* fc1_w  = (const float*)d_in[10];
    const float* fc1_b  = (const float*)d_in[11];
    const float* fc2_w  = (const float*)d_in[12];
    const float* fc2_b  = (const float*)d_in[13];
    float* out = (float*)d_out;

    float *h0, *h1, *h2, *h3, *h4;
    cudaGetSymbolAddress((void**)&h0, g_h0);
    cudaGetSymbolAddress((void**)&h1, g_h1);
    cudaGetSymbolAddress((void**)&h2, g_h2);
    cudaGetSymbolAddress((void**)&h3, g_h3);
    cudaGetSymbolAddress((void**)&h4, g_h4);

    const int NB = (N_NODES + 63) / 64;

    detect_idx_kernel<<<1, 32>>>(idxw);
    conv_idx_kernel<<<(N_NODES * SEQ + 255) / 256, 256>>>(idxw);
    fc0_kernel<<<(N_NODES + 255) / 256, 256>>>(x, fc0_w, fc0_b);

    // spiral conv 1: C=16, K=256, O=32
    gemm_elu_kernel<16, 256, 32, 32, true><<<dim3(NB, 1), 256>>>(h0, h1, w1, b1);
    // spiral conv 2: C=32, K=512, O=64
    gemm_elu_kernel<32, 512, 64, 64, true><<<dim3(NB, 1), 256>>>(h1, h2, w2, b2);
    // spiral conv 3: C=64, K=1024, O=128
    gemm_elu_kernel<64, 1024, 128, 128, true><<<dim3(NB, 1), 256>>>(h2, h3, w3, b3);
    // fc1 (dense): K=128, O=256 (2 output tiles of 128)
    gemm_elu_kernel<128, 128, 256, 128, false><<<dim3(NB, 2), 256>>>(h3, h4, fc1_w, fc1_b);
    // fc2 + log_softmax
    fc2_lsm_kernel<<<(N_NODES + 7) / 8, 256>>>(fc2_w, fc2_b, out);
}